// round 6
// baseline (speedup 1.0000x reference)
#include <cuda_runtime.h>
#include <cuda_fp16.h>
#include <mma.h>
#include <cstdint>

using namespace nvcuda;

// ---------------------------------------------------------------------------
// MambaRefiner: B=2, C=64, T=512, CH=8, D_MODEL=512, D_IN=1024, D_ST=128,
// DT_R=32, K=3, L=2.  fp32 I/O.
// GEMMs: 3xTF32 (hh + hl + lh) on the verified wmma tf32 path, but with
// operands PRE-SPLIT into [hi|lo] global buffers so the GEMM hot loop is a
// plain cp.async double-buffered tf32 GEMM over a virtual K' = 3K:
//   segment 0: Ah x Wh,  segment 1: Ah x Wl,  segment 2: Al x Wh
// ---------------------------------------------------------------------------

#define NROWS 1024              // B*T tokens

// ---- scratch layout (floats) ----
#define OFF_H2    0                        // 1024 x 1024   [hi|lo] of H (512)
#define OFF_XZ    (OFF_H2    + 1048576)    // 1024 x 2048
#define OFF_XS    (OFF_XZ    + 2097152)    // 1024 x 1024   plain (scan x)
#define OFF_XS2   (OFF_XS    + 1048576)    // 1024 x 2048   [hi|lo]
#define OFF_XD    (OFF_XS2   + 2097152)    // 1024 x 288    plain (scan B/C)
#define OFF_DT2   (OFF_XD    + 294912)     // 1024 x 64     [hi|lo] of dt (32)
#define OFF_DL    (OFF_DT2   + 65536)      // 1024 x 1024   delta
#define OFF_Y2    (OFF_DL    + 1048576)    // 1024 x 2048   [hi|lo]
#define OFF_IPW2  (OFF_Y2    + 2097152)    // 4096 x 1024
#define OFF_XPW2  (OFF_IPW2  + 4194304)    // 576  x 2048
#define OFF_DPW2  (OFF_XPW2  + 1179648)    // 2048 x 64
#define OFF_OPW2  (OFF_DPW2  + 131072)     // 1024 x 2048
#define OFF_FCW2  (OFF_OPW2  + 2097152)    // 512  x 1024
#define SCRATCH_TOTAL (OFF_FCW2 + 524288)

__device__ __align__(256) float g_scratch[SCRATCH_TOTAL];

__device__ __forceinline__ void tf32_split(float x, float& h, float& l) {
    h = wmma::__float_to_tf32(x);
    l = wmma::__float_to_tf32(x - h);
}

// ---------------------------------------------------------------------------
// Generic weight split: src (rows x K) -> dst (rows x 2K) as [hi | lo]
// ---------------------------------------------------------------------------
__global__ void k_split(const float* __restrict__ src, float* __restrict__ dst,
                        int K, int total) {
    int idx = blockIdx.x * blockDim.x + threadIdx.x;
    if (idx >= total) return;
    int r = idx / K, c = idx % K;
    float h, l;
    tf32_split(src[idx], h, l);
    dst[(size_t)r * 2 * K + c] = h;
    dst[(size_t)r * 2 * K + K + c] = l;
}

// ---------------------------------------------------------------------------
// Input transpose + split: H2[r, d]=hi, H2[r, 512+d]=lo of z_q[b,c,t,ch]
// ---------------------------------------------------------------------------
__global__ void k_transpose_in(const float* __restrict__ zq, float* __restrict__ H2) {
    int idx = blockIdx.x * blockDim.x + threadIdx.x;   // 1024*512
    int d = idx & 511;
    int r = idx >> 9;
    int t = r & 511;
    int b = r >> 9;
    float x = zq[((b * 64 + (d >> 3)) * 512 + t) * 8 + (d & 7)];
    float h, l;
    tf32_split(x, h, l);
    H2[r * 1024 + d] = h;
    H2[r * 1024 + 512 + d] = l;
}

// ---------------------------------------------------------------------------
// Causal depthwise conv K=3 + bias + SiLU; writes XS plain + XS2 [hi|lo]
// ---------------------------------------------------------------------------
__global__ void k_conv_silu(const float* __restrict__ xz,
                            const float* __restrict__ cw,
                            const float* __restrict__ cb,
                            float* __restrict__ xs,
                            float* __restrict__ xs2) {
    int idx = blockIdx.x * blockDim.x + threadIdx.x;   // 1024*1024
    int d = idx & 1023;
    int row = idx >> 10;
    int t = row & 511;
    float v = cb[d] + cw[d * 3 + 2] * xz[row * 2048 + d];
    if (t > 0) v += cw[d * 3 + 1] * xz[(row - 1) * 2048 + d];
    if (t > 1) v += cw[d * 3 + 0] * xz[(row - 2) * 2048 + d];
    float s = v / (1.0f + __expf(-v));
    xs[idx] = s;
    float h, l;
    tf32_split(s, h, l);
    xs2[row * 2048 + d] = h;
    xs2[row * 2048 + 1024 + d] = l;
}

// ---------------------------------------------------------------------------
// cp.async helpers
// ---------------------------------------------------------------------------
__device__ __forceinline__ void cp16(uint32_t smem_dst, const float* gsrc) {
    asm volatile("cp.async.cg.shared.global [%0], [%1], 16;\n"
                 :: "r"(smem_dst), "l"(gsrc));
}
__device__ __forceinline__ void cp_commit() {
    asm volatile("cp.async.commit_group;\n" ::: "memory");
}

// ---------------------------------------------------------------------------
// Plain tf32 GEMM over pre-split operands, virtual K' = 3K.
//   A2: (M x 2K) [hi|lo], W2: (N x 2K) [hi|lo]
//   seg 0: Ah*Wh   seg 1: Ah*Wl   seg 2: Al*Wh
// wmma m16n16k8 tf32, fp32 accumulate, cp.async double buffer, BK=32.
// 8 warps (256 threads); (BM/WM)*(BN/WN) == 8.
// EPI: 0 plain store; 1 softplus(acc+bias); 2 bias + scatter (b,c,t,ch);
//      3 plain store + tf32-split cols<32 into aux (1024 x 64);
//      4 tf32-split store into aux (width 2*ldc).
// ---------------------------------------------------------------------------
template<int BM, int BN, int BK, int WM, int WN, int EPI>
__global__ void __launch_bounds__(256)
k_tc(const float* __restrict__ A2, int lda2,
     const float* __restrict__ W2, int ldw2,
     float* __restrict__ C, int ldc, int K,
     const float* __restrict__ bias,
     float* __restrict__ out2,
     float* __restrict__ aux) {
    static_assert((BM / WM) * (BN / WN) == 8, "need 8 warps");
    constexpr int LDT = BK + 4;
    constexpr int BUF = (BM + BN) * LDT;          // floats per stage
    constexpr int NWN = BN / WN;
    constexpr int MI = WM / 16, NI = WN / 16;
    constexpr int LDCS = BN + 4;
    constexpr int NA4 = BM * BK / 1024;           // float4 loads per thread (A)
    constexpr int NW4 = BN * BK / 1024;           //   "  (W)
    __shared__ float sm[2 * BUF];

    const int tid = threadIdx.x;
    const int wid = tid >> 5;
    const int wm0 = (wid / NWN) * WM;
    const int wn0 = (wid % NWN) * WN;
    const int m0 = blockIdx.y * BM;
    const int n0 = blockIdx.x * BN;
    const int NSEG = K / BK;
    const int NIT = 3 * NSEG;

    wmma::fragment<wmma::accumulator, 16, 16, 8, float> acc[MI][NI];
#pragma unroll
    for (int i = 0; i < MI; i++)
#pragma unroll
        for (int j = 0; j < NI; j++) wmma::fill_fragment(acc[i][j], 0.0f);

    auto issue_load = [&](int it, int p) {
        int seg = it / NSEG;
        int ks = (it - seg * NSEG) * BK;
        int aoff = (seg == 2 ? K : 0) + ks;       // A: hi, hi, lo
        int woff = (seg == 1 ? K : 0) + ks;       // W: hi, lo, hi
        float* As = sm + p * BUF;
        float* Ws = As + BM * LDT;
#pragma unroll
        for (int u = 0; u < NA4; u++) {
            int i = tid + u * 256;
            int r = i / (BK / 4), q = i - r * (BK / 4);
            uint32_t d = (uint32_t)__cvta_generic_to_shared(&As[r * LDT + q * 4]);
            cp16(d, &A2[(size_t)(m0 + r) * lda2 + aoff + q * 4]);
        }
#pragma unroll
        for (int u = 0; u < NW4; u++) {
            int i = tid + u * 256;
            int r = i / (BK / 4), q = i - r * (BK / 4);
            uint32_t d = (uint32_t)__cvta_generic_to_shared(&Ws[r * LDT + q * 4]);
            cp16(d, &W2[(size_t)(n0 + r) * ldw2 + woff + q * 4]);
        }
        cp_commit();
    };

    issue_load(0, 0);
    for (int it = 0; it < NIT; it++) {
        int p = it & 1;
        if (it + 1 < NIT) {
            issue_load(it + 1, p ^ 1);
            asm volatile("cp.async.wait_group 1;\n" ::: "memory");
        } else {
            asm volatile("cp.async.wait_group 0;\n" ::: "memory");
        }
        __syncthreads();

        const float* As = sm + p * BUF;
        const float* Ws = As + BM * LDT;
#pragma unroll
        for (int kk = 0; kk < BK; kk += 8) {
            wmma::fragment<wmma::matrix_a, 16, 16, 8, wmma::precision::tf32, wmma::row_major> fa[MI];
            wmma::fragment<wmma::matrix_b, 16, 16, 8, wmma::precision::tf32, wmma::col_major> fb[NI];
#pragma unroll
            for (int i = 0; i < MI; i++)
                wmma::load_matrix_sync(fa[i], As + (wm0 + 16 * i) * LDT + kk, LDT);
#pragma unroll
            for (int j = 0; j < NI; j++)
                wmma::load_matrix_sync(fb[j], Ws + (wn0 + 16 * j) * LDT + kk, LDT);
#pragma unroll
            for (int i = 0; i < MI; i++)
#pragma unroll
                for (int j = 0; j < NI; j++)
                    wmma::mma_sync(acc[i][j], fa[i], fb[j], acc[i][j]);
        }
        __syncthreads();
    }

    if (EPI == 0) {
#pragma unroll
        for (int i = 0; i < MI; i++)
#pragma unroll
            for (int j = 0; j < NI; j++)
                wmma::store_matrix_sync(&C[(size_t)(m0 + wm0 + 16 * i) * ldc + n0 + wn0 + 16 * j],
                                        acc[i][j], ldc, wmma::mem_row_major);
    } else {
        // stage accumulators to smem, then elementwise epilogue
#pragma unroll
        for (int i = 0; i < MI; i++)
#pragma unroll
            for (int j = 0; j < NI; j++)
                wmma::store_matrix_sync(&sm[(wm0 + 16 * i) * LDCS + wn0 + 16 * j],
                                        acc[i][j], LDCS, wmma::mem_row_major);
        __syncthreads();
        for (int i = tid; i < BM * BN; i += 256) {
            int r = i / BN, c = i - (i / BN) * BN;
            int row = m0 + r, col = n0 + c;
            float v = sm[r * LDCS + c];
            if (EPI == 1) {
                v += bias[col];
                float sp = (v > 20.0f) ? v : log1pf(__expf(v));
                C[(size_t)row * ldc + col] = sp;
            } else if (EPI == 2) {
                v += bias[col];
                int b = row >> 9;
                int t = row & 511;
                out2[b * 262144 + (col >> 3) * 4096 + t * 8 + (col & 7)] = v;
            } else if (EPI == 3) {
                C[(size_t)row * ldc + col] = v;
                if (col < 32) {
                    float h, l;
                    tf32_split(v, h, l);
                    aux[row * 64 + col] = h;
                    aux[row * 64 + 32 + col] = l;
                }
            } else { // EPI == 4: [hi|lo] store into aux (width 2*ldc)
                float h, l;
                tf32_split(v, h, l);
                aux[(size_t)row * 2 * ldc + col] = h;
                aux[(size_t)row * 2 * ldc + ldc + col] = l;
            }
        }
    }
}

// ---------------------------------------------------------------------------
// Selective scan.  grid = (128, 2): blockIdx.y = batch, 8 warps/block,
// warp w handles channel d = blockIdx.x*8 + w, 4 states per lane.
// Output written as [hi|lo] into Y2 (1024 x 2048).
// ---------------------------------------------------------------------------
__global__ void __launch_bounds__(256)
k_scan(const float* __restrict__ xdbl,    // (1024, 288): [dt | B | C]
       const float* __restrict__ delta,   // (1024, 1024)
       const float* __restrict__ xs,      // (1024, 1024)
       const float* __restrict__ xz,      // (1024, 2048), z = cols [1024:2048)
       const float* __restrict__ alog,    // (1024, 128)
       const float* __restrict__ Dp,      // (1024,)
       float* __restrict__ y2) {          // (1024, 2048) [hi|lo]
    const int b = blockIdx.y;
    const int w = threadIdx.x >> 5;
    const int lane = threadIdx.x & 31;
    const int d = blockIdx.x * 8 + w;

    __shared__ float Bs[32][128];
    __shared__ float Cs[32][128];
    __shared__ float dsh[32][8];
    __shared__ float xsh[32][8];
    __shared__ float zsh[32][8];

    const float* Ap = alog + d * 128 + lane * 4;
    float A0 = -expf(Ap[0]);
    float A1 = -expf(Ap[1]);
    float A2 = -expf(Ap[2]);
    float A3 = -expf(Ap[3]);
    float Dd = Dp[d];

    float h0 = 0.f, h1 = 0.f, h2 = 0.f, h3 = 0.f;
    const int rowbase = b * 512;

    for (int tc = 0; tc < 512; tc += 32) {
        for (int i = threadIdx.x; i < 32 * 32; i += 256) {
            int tt = i >> 5, sq = i & 31;
            int row = rowbase + tc + tt;
            *(float4*)&Bs[tt][sq * 4] = *(const float4*)&xdbl[row * 288 + 32 + sq * 4];
            *(float4*)&Cs[tt][sq * 4] = *(const float4*)&xdbl[row * 288 + 160 + sq * 4];
        }
        if (threadIdx.x < 32 * 8) {
            int tt = threadIdx.x >> 3, dd = threadIdx.x & 7;
            int row = rowbase + tc + tt;
            int dcol = blockIdx.x * 8 + dd;
            dsh[tt][dd] = delta[row * 1024 + dcol];
            xsh[tt][dd] = xs[row * 1024 + dcol];
            zsh[tt][dd] = xz[row * 2048 + 1024 + dcol];
        }
        __syncthreads();

        for (int tt = 0; tt < 32; tt++) {
            float dv = dsh[tt][w];
            float xv = xsh[tt][w];
            float dx = dv * xv;
            float4 Bv = *(float4*)&Bs[tt][lane * 4];
            float4 Cv = *(float4*)&Cs[tt][lane * 4];
            h0 = __expf(dv * A0) * h0 + dx * Bv.x;
            h1 = __expf(dv * A1) * h1 + dx * Bv.y;
            h2 = __expf(dv * A2) * h2 + dx * Bv.z;
            h3 = __expf(dv * A3) * h3 + dx * Bv.w;
            float acc = h0 * Cv.x + h1 * Cv.y + h2 * Cv.z + h3 * Cv.w;
            acc += __shfl_xor_sync(0xffffffffu, acc, 16);
            acc += __shfl_xor_sync(0xffffffffu, acc, 8);
            acc += __shfl_xor_sync(0xffffffffu, acc, 4);
            acc += __shfl_xor_sync(0xffffffffu, acc, 2);
            acc += __shfl_xor_sync(0xffffffffu, acc, 1);
            if (lane == 0) {
                float yy = acc + xv * Dd;
                float zv = zsh[tt][w];
                float sz = zv / (1.0f + __expf(-zv));
                float yv = yy * sz;
                float h, l;
                tf32_split(yv, h, l);
                int row = rowbase + tc + tt;
                y2[row * 2048 + d] = h;
                y2[row * 2048 + 1024 + d] = l;
            }
        }
        __syncthreads();
    }
}

// ---------------------------------------------------------------------------
extern "C" void kernel_launch(void* const* d_in, const int* in_sizes, int n_in,
                              void* d_out, int out_size) {
    const float* z_q  = (const float*)d_in[0];
    const float* ipw  = (const float*)d_in[1];   // (2, 2048, 512)
    const float* cw   = (const float*)d_in[2];   // (2, 1024, 3)
    const float* cb   = (const float*)d_in[3];   // (2, 1024)
    const float* xpw  = (const float*)d_in[4];   // (2, 288, 1024)
    const float* dpw  = (const float*)d_in[5];   // (2, 1024, 32)
    const float* dpb  = (const float*)d_in[6];   // (2, 1024)
    const float* alog = (const float*)d_in[7];   // (2, 1024, 128)
    const float* Dp   = (const float*)d_in[8];   // (2, 1024)
    const float* opw  = (const float*)d_in[9];   // (2, 512, 1024)
    const float* fcw  = (const float*)d_in[10];  // (512, 512)
    const float* fcb  = (const float*)d_in[11];  // (512,)
    float* out = (float*)d_out;

    float* S = nullptr;
    cudaGetSymbolAddress((void**)&S, g_scratch);
    float* H2   = S + OFF_H2;
    float* XZ   = S + OFF_XZ;
    float* XS   = S + OFF_XS;
    float* XS2  = S + OFF_XS2;
    float* XD   = S + OFF_XD;
    float* DT2  = S + OFF_DT2;
    float* DL   = S + OFF_DL;
    float* Y2   = S + OFF_Y2;
    float* IPW2 = S + OFF_IPW2;
    float* XPW2 = S + OFF_XPW2;
    float* DPW2 = S + OFF_DPW2;
    float* OPW2 = S + OFF_OPW2;
    float* FCW2 = S + OFF_FCW2;

    // weight splits (every call; weights are inputs)
    k_split<<<(4096 * 512 + 255) / 256, 256>>>(ipw, IPW2, 512, 4096 * 512);
    k_split<<<(576 * 1024 + 255) / 256, 256>>>(xpw, XPW2, 1024, 576 * 1024);
    k_split<<<(2048 * 32 + 255) / 256, 256>>>(dpw, DPW2, 32, 2048 * 32);
    k_split<<<(1024 * 1024 + 255) / 256, 256>>>(opw, OPW2, 1024, 1024 * 1024);
    k_split<<<(512 * 512 + 255) / 256, 256>>>(fcw, FCW2, 512, 512 * 512);

    k_transpose_in<<<NROWS * 512 / 256, 256>>>(z_q, H2);

    for (int l = 0; l < 2; l++) {
        // xz = H @ ipw^T : (1024, 2048), K=512
        k_tc<64, 64, 32, 16, 32, 0><<<dim3(2048 / 64, 1024 / 64), 256>>>(
            H2, 1024, IPW2 + (size_t)l * 2048 * 1024, 1024,
            XZ, 2048, 512, nullptr, nullptr, nullptr);

        // conv + silu -> XS, XS2
        k_conv_silu<<<NROWS * 1024 / 256, 256>>>(XZ, cw + l * 1024 * 3, cb + l * 1024,
                                                 XS, XS2);

        // x_dbl = XS @ xpw^T : (1024, 288), K=1024; split dt cols into DT2
        k_tc<64, 32, 32, 16, 16, 3><<<dim3(288 / 32, 1024 / 64), 256>>>(
            XS2, 2048, XPW2 + (size_t)l * 288 * 2048, 2048,
            XD, 288, 1024, nullptr, nullptr, DT2);

        // delta = softplus(dt @ dpw^T + dpb) : (1024, 1024), K=32
        k_tc<64, 64, 32, 16, 32, 1><<<dim3(1024 / 64, 1024 / 64), 256>>>(
            DT2, 64, DPW2 + (size_t)l * 1024 * 64, 64,
            DL, 1024, 32, dpb + l * 1024, nullptr, nullptr);

        // selective scan -> Y2 [hi|lo]
        k_scan<<<dim3(128, 2), 256>>>(XD, DL, XS, XZ,
                                      alog + l * 1024 * 128, Dp + l * 1024, Y2);

        // H = Y @ opw^T : (1024, 512), K=1024 -> H2 [hi|lo]
        k_tc<64, 64, 32, 16, 32, 4><<<dim3(512 / 64, 1024 / 64), 256>>>(
            Y2, 2048, OPW2 + (size_t)l * 512 * 2048, 2048,
            nullptr, 512, 1024, nullptr, nullptr, H2);
    }

    // out = (H @ fcw^T + fcb) scattered to (b, c, t, ch), K=512
    k_tc<64, 64, 32, 16, 32, 2><<<dim3(512 / 64, 1024 / 64), 256>>>(
        H2, 1024, FCW2, 1024,
        nullptr, 512, 512, fcb, out, nullptr);
}

// round 7
// speedup vs baseline: 1.5071x; 1.5071x over previous
#include <cuda_runtime.h>
#include <cstdint>

// ---------------------------------------------------------------------------
// MambaRefiner: B=2, C=64, T=512, CH=8, D_MODEL=512, D_IN=1024, D_ST=128,
// DT_R=32, K=3, L=2.  All fp32 (round-1 verified skeleton).
// Round-7 change: split-K two-pass GEMMs + 128-thread 8x4 / 4x4 micro-tiles
// to raise resident warps/SM from ~8 to ~28-56 (the round-1..6 bottleneck).
// ---------------------------------------------------------------------------

#define NROWS 1024          // B*T tokens

// scratch layout (floats)
#define OFF_H     0                        // 1024 x 512
#define OFF_XZ    (OFF_H    + 524288)      // 1024 x 2048
#define OFF_XS    (OFF_XZ   + 2097152)     // 1024 x 1024
#define OFF_XD    (OFF_XS   + 1048576)     // 1024 x 288
#define OFF_DL    (OFF_XD   + 294912)      // 1024 x 1024
#define OFF_Y     (OFF_DL   + 1048576)     // 1024 x 1024
#define OFF_PTI   (OFF_Y    + 1048576)     // 2 x 1024 x 2048
#define OFF_PTX   (OFF_PTI  + 4194304)     // 4 x 1024 x 288
#define OFF_PTO   (OFF_PTX  + 1179648)     // 4 x 1024 x 512
#define OFF_PTF   (OFF_PTO  + 2097152)     // 2 x 1024 x 512
#define SCRATCH_TOTAL (OFF_PTF + 1048576)

__device__ __align__(256) float g_scratch[SCRATCH_TOTAL];

// ---------------------------------------------------------------------------
// Input transpose: h[b,t,c*8+ch] = z_q[b,c,t,ch]
// ---------------------------------------------------------------------------
__global__ void k_transpose_in(const float* __restrict__ zq, float* __restrict__ h) {
    int idx = blockIdx.x * blockDim.x + threadIdx.x;   // 1024*512
    int d = idx & 511;
    int r = idx >> 9;
    int t = r & 511;
    int b = r >> 9;
    h[idx] = zq[((b * 64 + (d >> 3)) * 512 + t) * 8 + (d & 7)];
}

// ---------------------------------------------------------------------------
// Causal depthwise conv K=3 + bias + SiLU on x (first 1024 cols of xz)
// ---------------------------------------------------------------------------
__global__ void k_conv_silu(const float* __restrict__ xz,
                            const float* __restrict__ cw,
                            const float* __restrict__ cb,
                            float* __restrict__ xs) {
    int idx = blockIdx.x * blockDim.x + threadIdx.x;   // 1024*1024
    int d = idx & 1023;
    int row = idx >> 10;
    int t = row & 511;
    float v = cb[d] + cw[d * 3 + 2] * xz[row * 2048 + d];
    if (t > 0) v += cw[d * 3 + 1] * xz[(row - 1) * 2048 + d];
    if (t > 1) v += cw[d * 3 + 0] * xz[(row - 2) * 2048 + d];
    xs[idx] = v / (1.0f + __expf(-v));
}

// ---------------------------------------------------------------------------
// Tiled SGEMM with split-K:  C[z][m,n] = sum_{k in seg z} A[m,k] * W[n,k]
// A, W are K-major fp32.  blockIdx.z selects the K segment of length KSEG;
// partial written at C + z*segStride (segStride=0 -> no split, full K pass).
// EPI: 0 = plain store, 1 = softplus(acc + bias[n]).
// blockDim.x must be (BM/TM)*(BN/TN).  M%BM==0, N%BN==0, KSEG%BK==0.
// ---------------------------------------------------------------------------
template<int BM, int BN, int BK, int TM, int TN, int EPI>
__global__ void __launch_bounds__((BM/TM)*(BN/TN))
k_sgemm(const float* __restrict__ A, int lda,
        const float* __restrict__ W, int ldw,
        float* __restrict__ C, int ldc, int KSEG, size_t segStride,
        const float* __restrict__ bias) {
    constexpr int NTHR = (BM / TM) * (BN / TN);
    constexpr int NX = BN / TN;
    __shared__ float As[BK][BM + 4];
    __shared__ float Ws[BK][BN + 4];

    const int tid = threadIdx.x;
    const int tx = tid % NX;
    const int ty = tid / NX;
    const int m0 = blockIdx.y * BM;
    const int n0 = blockIdx.x * BN;
    const int k0 = blockIdx.z * KSEG;
    float* Cp = C + (size_t)blockIdx.z * segStride;

    float acc[TM][TN];
#pragma unroll
    for (int i = 0; i < TM; i++)
#pragma unroll
        for (int j = 0; j < TN; j++) acc[i][j] = 0.0f;

    for (int kt = 0; kt < KSEG; kt += BK) {
        const int kb = k0 + kt;
        for (int i = tid; i < BM * BK / 4; i += NTHR) {
            int r = i / (BK / 4);
            int kq = i % (BK / 4);
            float4 v = *(const float4*)&A[(size_t)(m0 + r) * lda + kb + kq * 4];
            As[kq * 4 + 0][r] = v.x;
            As[kq * 4 + 1][r] = v.y;
            As[kq * 4 + 2][r] = v.z;
            As[kq * 4 + 3][r] = v.w;
        }
        for (int i = tid; i < BN * BK / 4; i += NTHR) {
            int r = i / (BK / 4);
            int kq = i % (BK / 4);
            float4 v = *(const float4*)&W[(size_t)(n0 + r) * ldw + kb + kq * 4];
            Ws[kq * 4 + 0][r] = v.x;
            Ws[kq * 4 + 1][r] = v.y;
            Ws[kq * 4 + 2][r] = v.z;
            Ws[kq * 4 + 3][r] = v.w;
        }
        __syncthreads();

#pragma unroll
        for (int kk = 0; kk < BK; kk++) {
            float a[TM], b[TN];
#pragma unroll
            for (int i4 = 0; i4 < TM / 4; i4++)
                *(float4*)&a[i4 * 4] = *(const float4*)&As[kk][ty * TM + i4 * 4];
#pragma unroll
            for (int j4 = 0; j4 < TN / 4; j4++)
                *(float4*)&b[j4 * 4] = *(const float4*)&Ws[kk][tx * TN + j4 * 4];
#pragma unroll
            for (int i = 0; i < TM; i++)
#pragma unroll
                for (int j = 0; j < TN; j++) acc[i][j] = fmaf(a[i], b[j], acc[i][j]);
        }
        __syncthreads();
    }

#pragma unroll
    for (int i = 0; i < TM; i++) {
        int row = m0 + ty * TM + i;
#pragma unroll
        for (int j = 0; j < TN; j++) {
            int col = n0 + tx * TN + j;
            float v = acc[i][j];
            if (EPI == 0) {
                Cp[(size_t)row * ldc + col] = v;
            } else { // softplus(acc + bias)
                v += bias[col];
                float sp = (v > 20.0f) ? v : log1pf(__expf(v));
                Cp[(size_t)row * ldc + col] = sp;
            }
        }
    }
}

// ---------------------------------------------------------------------------
// Split-K reducers
// ---------------------------------------------------------------------------
__global__ void k_reduce(const float* __restrict__ pt, float* __restrict__ out,
                         int MN, int segs) {
    int idx = blockIdx.x * blockDim.x + threadIdx.x;
    if (idx >= MN) return;
    float s = 0.0f;
    for (int z = 0; z < segs; z++) s += pt[(size_t)z * MN + idx];
    out[idx] = s;
}

// fc reduce: sum + bias + scatter to (b, c, t, ch)
__global__ void k_reduce_fc(const float* __restrict__ pt,
                            const float* __restrict__ bias,
                            float* __restrict__ out, int MN, int segs) {
    int idx = blockIdx.x * blockDim.x + threadIdx.x;   // row*512+col
    if (idx >= MN) return;
    float s = 0.0f;
    for (int z = 0; z < segs; z++) s += pt[(size_t)z * MN + idx];
    int row = idx >> 9;
    int col = idx & 511;
    s += bias[col];
    int b = row >> 9;
    int t = row & 511;
    out[b * 262144 + (col >> 3) * 4096 + t * 8 + (col & 7)] = s;
}

// ---------------------------------------------------------------------------
// Selective scan.  grid = (128, 2): blockIdx.y = batch, 8 warps/block,
// warp w handles channel d = blockIdx.x*8 + w, 4 states per lane.
// ---------------------------------------------------------------------------
__global__ void __launch_bounds__(256)
k_scan(const float* __restrict__ xdbl,    // (1024, 288): [dt | B | C]
       const float* __restrict__ delta,   // (1024, 1024)
       const float* __restrict__ xs,      // (1024, 1024)
       const float* __restrict__ xz,      // (1024, 2048), z = cols [1024:2048)
       const float* __restrict__ alog,    // (1024, 128)
       const float* __restrict__ Dp,      // (1024,)
       float* __restrict__ y) {           // (1024, 1024)
    const int b = blockIdx.y;
    const int w = threadIdx.x >> 5;
    const int lane = threadIdx.x & 31;
    const int d = blockIdx.x * 8 + w;

    __shared__ float Bs[32][128];
    __shared__ float Cs[32][128];
    __shared__ float dsh[32][8];
    __shared__ float xsh[32][8];
    __shared__ float zsh[32][8];

    const float* Ap = alog + d * 128 + lane * 4;
    float A0 = -expf(Ap[0]);
    float A1 = -expf(Ap[1]);
    float A2 = -expf(Ap[2]);
    float A3 = -expf(Ap[3]);
    float Dd = Dp[d];

    float h0 = 0.f, h1 = 0.f, h2 = 0.f, h3 = 0.f;
    const int rowbase = b * 512;

    for (int tc = 0; tc < 512; tc += 32) {
        for (int i = threadIdx.x; i < 32 * 32; i += 256) {
            int tt = i >> 5, sq = i & 31;
            int row = rowbase + tc + tt;
            *(float4*)&Bs[tt][sq * 4] = *(const float4*)&xdbl[row * 288 + 32 + sq * 4];
            *(float4*)&Cs[tt][sq * 4] = *(const float4*)&xdbl[row * 288 + 160 + sq * 4];
        }
        if (threadIdx.x < 32 * 8) {
            int tt = threadIdx.x >> 3, dd = threadIdx.x & 7;
            int row = rowbase + tc + tt;
            int dcol = blockIdx.x * 8 + dd;
            dsh[tt][dd] = delta[row * 1024 + dcol];
            xsh[tt][dd] = xs[row * 1024 + dcol];
            zsh[tt][dd] = xz[row * 2048 + 1024 + dcol];
        }
        __syncthreads();

        for (int tt = 0; tt < 32; tt++) {
            float dv = dsh[tt][w];
            float xv = xsh[tt][w];
            float dx = dv * xv;
            float4 Bv = *(float4*)&Bs[tt][lane * 4];
            float4 Cv = *(float4*)&Cs[tt][lane * 4];
            h0 = __expf(dv * A0) * h0 + dx * Bv.x;
            h1 = __expf(dv * A1) * h1 + dx * Bv.y;
            h2 = __expf(dv * A2) * h2 + dx * Bv.z;
            h3 = __expf(dv * A3) * h3 + dx * Bv.w;
            float acc = h0 * Cv.x + h1 * Cv.y + h2 * Cv.z + h3 * Cv.w;
            acc += __shfl_xor_sync(0xffffffffu, acc, 16);
            acc += __shfl_xor_sync(0xffffffffu, acc, 8);
            acc += __shfl_xor_sync(0xffffffffu, acc, 4);
            acc += __shfl_xor_sync(0xffffffffu, acc, 2);
            acc += __shfl_xor_sync(0xffffffffu, acc, 1);
            if (lane == 0) {
                float yy = acc + xv * Dd;
                float zv = zsh[tt][w];
                float sz = zv / (1.0f + __expf(-zv));
                y[(rowbase + tc + tt) * 1024 + d] = yy * sz;
            }
        }
        __syncthreads();
    }
}

// ---------------------------------------------------------------------------
extern "C" void kernel_launch(void* const* d_in, const int* in_sizes, int n_in,
                              void* d_out, int out_size) {
    const float* z_q  = (const float*)d_in[0];
    const float* ipw  = (const float*)d_in[1];   // (2, 2048, 512)
    const float* cw   = (const float*)d_in[2];   // (2, 1024, 3)
    const float* cb   = (const float*)d_in[3];   // (2, 1024)
    const float* xpw  = (const float*)d_in[4];   // (2, 288, 1024)
    const float* dpw  = (const float*)d_in[5];   // (2, 1024, 32)
    const float* dpb  = (const float*)d_in[6];   // (2, 1024)
    const float* alog = (const float*)d_in[7];   // (2, 1024, 128)
    const float* Dp   = (const float*)d_in[8];   // (2, 1024)
    const float* opw  = (const float*)d_in[9];   // (2, 512, 1024)
    const float* fcw  = (const float*)d_in[10];  // (512, 512)
    const float* fcb  = (const float*)d_in[11];  // (512,)
    float* out = (float*)d_out;

    float* S = nullptr;
    cudaGetSymbolAddress((void**)&S, g_scratch);
    float* H   = S + OFF_H;
    float* XZ  = S + OFF_XZ;
    float* XS  = S + OFF_XS;
    float* XD  = S + OFF_XD;
    float* DL  = S + OFF_DL;
    float* Y   = S + OFF_Y;
    float* PTI = S + OFF_PTI;
    float* PTX = S + OFF_PTX;
    float* PTO = S + OFF_PTO;
    float* PTF = S + OFF_PTF;

    k_transpose_in<<<NROWS * 512 / 256, 256>>>(z_q, H);

    for (int l = 0; l < 2; l++) {
        // xz = H @ ipw^T : (1024, 2048), K=512 split 2 -> 1024 blocks
        k_sgemm<64, 64, 32, 8, 4, 0><<<dim3(2048 / 64, 1024 / 64, 2), 128>>>(
            H, 512, ipw + (size_t)l * 2048 * 512, 512,
            PTI, 2048, 256, (size_t)1024 * 2048, nullptr);
        k_reduce<<<(1024 * 2048 + 255) / 256, 256>>>(PTI, XZ, 1024 * 2048, 2);

        // conv + silu -> XS (1024, 1024)
        k_conv_silu<<<NROWS * 1024 / 256, 256>>>(XZ, cw + l * 1024 * 3, cb + l * 1024, XS);

        // x_dbl = XS @ xpw^T : (1024, 288), K=1024 split 4 -> 576 blocks
        k_sgemm<64, 32, 32, 4, 4, 0><<<dim3(288 / 32, 1024 / 64, 4), 128>>>(
            XS, 1024, xpw + (size_t)l * 288 * 1024, 1024,
            PTX, 288, 256, (size_t)1024 * 288, nullptr);
        k_reduce<<<(1024 * 288 + 255) / 256, 256>>>(PTX, XD, 1024 * 288, 4);

        // delta = softplus(dt @ dpw^T + dpb) : (1024, 1024), K=32 (no split)
        k_sgemm<64, 64, 32, 8, 4, 1><<<dim3(1024 / 64, 1024 / 64, 1), 128>>>(
            XD, 288, dpw + (size_t)l * 1024 * 32, 32,
            DL, 1024, 32, 0, dpb + l * 1024);

        // selective scan -> Y
        k_scan<<<dim3(128, 2), 256>>>(XD, DL, XS, XZ,
                                      alog + (size_t)l * 1024 * 128, Dp + l * 1024, Y);

        // H = Y @ opw^T : (1024, 512), K=1024 split 4 -> 512 blocks
        k_sgemm<64, 64, 32, 8, 4, 0><<<dim3(512 / 64, 1024 / 64, 4), 128>>>(
            Y, 1024, opw + (size_t)l * 512 * 1024, 1024,
            PTO, 512, 256, (size_t)1024 * 512, nullptr);
        k_reduce<<<(1024 * 512 + 255) / 256, 256>>>(PTO, H, 1024 * 512, 4);
    }

    // out = H @ fcw^T + fcb : (1024, 512), K=512 split 2 -> 256 blocks
    k_sgemm<64, 64, 32, 8, 4, 0><<<dim3(512 / 64, 1024 / 64, 2), 128>>>(
        H, 512, fcw, 512, PTF, 512, 256, (size_t)1024 * 512, nullptr);
    k_reduce_fc<<<(1024 * 512 + 255) / 256, 256>>>(PTF, fcb, out, 1024 * 512, 2);
}